// round 1
// baseline (speedup 1.0000x reference)
#include <cuda_runtime.h>
#include <math.h>

// ---------------------------------------------------------------------------
// Quantum circuit collapsed analytically:
//   amp(b,s)  = (1/32) * exp(i*pi*A),  A = S + (S^2 - Q)/2
//   M = E R E with E = prefix-XOR permutation pi, R = tensor of 2x2 gates
//   out(b)    = cos(th)*(P1-P0) + 2 sin(th)*Re<x0,x1> over pairs (k, k^768)
// ---------------------------------------------------------------------------

#define NQ 10
#define DIM 1024
#define HALF 512
#define NT 256

__device__ int    g_flag;          // inputs.max() > 1 ?
__device__ float2 g_gate[NQ][4];   // Rx(wx*2pi) @ Rz(wz*2pi) per qubit
__device__ float  g_costh, g_sinth;

__global__ void k_reset() { g_flag = 0; }

__global__ void k_flag(const float* __restrict__ in, int n) {
    int i = blockIdx.x * blockDim.x + threadIdx.x;
    int stride = gridDim.x * blockDim.x;
    int p = 0;
    for (; i < n; i += stride) p |= (in[i] > 1.0f);
    if (__syncthreads_or(p)) {
        if (threadIdx.x == 0) atomicOr(&g_flag, 1);
    }
}

__global__ void k_gates(const float* __restrict__ w) {
    int q = threadIdx.x;
    if (q < NQ) {
        float sx, cx, sz, cz;
        sincospif(w[3 + q], &sx, &cx);        // Rx half-angle = pi*w
        sincospif(w[3 + NQ + q], &sz, &cz);   // Rz half-angle = pi*w
        // G = Rx @ Rz
        g_gate[q][0] = make_float2( cx * cz, -cx * sz);
        g_gate[q][1] = make_float2( sx * sz, -sx * cz);
        g_gate[q][2] = make_float2(-sx * sz, -sx * cz);
        g_gate[q][3] = make_float2( cx * cz,  cx * sz);
    }
    if (q == 0) {
        float s, c;
        sincospif(2.0f * (w[0] + w[1] + w[2]), &s, &c); // theta = 2pi*sum(w)
        g_costh = c; g_sinth = s;
    }
}

__global__ __launch_bounds__(NT) void k_main(const float* __restrict__ in,
                                             float* __restrict__ out) {
    __shared__ float2 amp[DIM];
    __shared__ float  sLo[32], sHi[32], xs[NQ];
    __shared__ float  sQ;
    __shared__ float  wsum[NT / 32];

    const int b = blockIdx.x;
    const int t = threadIdx.x;
    const int flag = g_flag;

    if (t < NQ) {
        float x = in[b * NQ + t];
        if (flag) x = atanf(x);
        xs[t] = x;
    }
    __syncthreads();

    // Half subset-sum tables.
    // State bit p (LSB=0) corresponds to qubit 9-p (MSB-first qubit index).
    if (t < 32) {
        float s = 0.0f;
        #pragma unroll
        for (int p = 0; p < 5; p++)
            s += ((t >> p) & 1) ? xs[9 - p] : -xs[9 - p];
        sLo[t] = s;
    } else if (t < 64) {
        int m = t - 32;
        float s = 0.0f;
        #pragma unroll
        for (int p = 0; p < 5; p++)
            s += ((m >> p) & 1) ? xs[4 - p] : -xs[4 - p];
        sHi[m] = s;
    } else if (t == 64) {
        float q = 0.0f;
        #pragma unroll
        for (int i = 0; i < NQ; i++) q += xs[i] * xs[i];
        sQ = q;
    }
    __syncthreads();

    const float Q = sQ;

    // Build state: amp at permuted index pi(s) (so butterflies see u = vec∘pi^-1)
    #pragma unroll
    for (int r = 0; r < DIM / NT; r++) {
        int s = t + r * NT;
        float S = sHi[s >> 5] + sLo[s & 31];
        float A = S + 0.5f * (S * S - Q);
        float sn, cs;
        sincospif(A, &sn, &cs);
        int p = s ^ (s >> 1);
        p ^= p >> 2;
        p ^= p >> 4;
        p ^= p >> 8;                  // pi(s): suffix parity
        amp[p] = make_float2(cs * 0.03125f, sn * 0.03125f);
    }
    __syncthreads();

    // 10 butterfly stages: qubit q acts on bit (9-q)
    #pragma unroll
    for (int q = 0; q < NQ; q++) {
        const int d = 1 << (9 - q);
        const float2 G00 = g_gate[q][0];
        const float2 G01 = g_gate[q][1];
        const float2 G10 = g_gate[q][2];
        const float2 G11 = g_gate[q][3];
        #pragma unroll
        for (int r = 0; r < HALF / NT; r++) {
            int i = t + r * NT;                       // pair index 0..511
            int k = ((i & ~(d - 1)) << 1) | (i & (d - 1));
            float2 a = amp[k];
            float2 c = amp[k + d];
            float2 w0, w1;
            w0.x = G00.x * a.x - G00.y * a.y + G01.x * c.x - G01.y * c.y;
            w0.y = G00.x * a.y + G00.y * a.x + G01.x * c.y + G01.y * c.x;
            w1.x = G10.x * a.x - G10.y * a.y + G11.x * c.x - G11.y * c.y;
            w1.y = G10.x * a.y + G10.y * a.x + G11.x * c.y + G11.y * c.x;
            amp[k]     = w0;
            amp[k + d] = w1;
        }
        __syncthreads();
    }

    // Output reduction: pairs (k, k^768), k has bit9 = 0
    const float cth  = g_costh;
    const float sth2 = 2.0f * g_sinth;
    float acc = 0.0f;
    #pragma unroll
    for (int r = 0; r < HALF / NT; r++) {
        int k = t + r * NT;           // k in [0,512): bit9 = 0
        float2 w0 = amp[k];
        float2 w1 = amp[k ^ 768];
        acc += cth  * ((w1.x * w1.x + w1.y * w1.y) - (w0.x * w0.x + w0.y * w0.y))
             + sth2 * (w0.x * w1.x + w0.y * w1.y);
    }
    #pragma unroll
    for (int o = 16; o; o >>= 1) acc += __shfl_xor_sync(0xFFFFFFFFu, acc, o);
    if ((t & 31) == 0) wsum[t >> 5] = acc;
    __syncthreads();
    if (t < NT / 32) {
        acc = wsum[t];
        #pragma unroll
        for (int o = (NT / 64); o; o >>= 1)
            acc += __shfl_xor_sync(0xFFu, acc, o);
        if (t == 0) out[b] = acc;
    }
}

extern "C" void kernel_launch(void* const* d_in, const int* in_sizes, int n_in,
                              void* d_out, int out_size) {
    const float* inputs = (const float*)d_in[0];   // [8192, 10]
    const float* weight = (const float*)d_in[1];   // [23]
    // d_in[2] = entangle_matrix: fixed CNOT cascade, replaced by closed-form perm
    float* out = (float*)d_out;                    // [8192]

    const int batch = in_sizes[0] / NQ;
    const int n_elems = in_sizes[0];

    k_reset<<<1, 1>>>();
    k_flag<<<160, 512>>>(inputs, n_elems);
    k_gates<<<1, 32>>>(weight);
    k_main<<<batch, NT>>>(inputs, out);
}

// round 2
// speedup vs baseline: 1.7426x; 1.7426x over previous
#include <cuda_runtime.h>
#include <math.h>

// ---------------------------------------------------------------------------
// Quantum circuit collapsed analytically:
//   amp(b,s)  = (1/32) * exp(i*pi*A),  A = S + (S^2 - Q)/2
//   M = E R E with E = suffix-parity permutation pi (pi^-1 = Gray code)
//   out(b)    = cos(th)*(P1-P0) + 2 sin(th)*Re<x0,x1> over pairs (k, k^768)
//
// R2: whole 1024-amp state lives in registers, ONE WARP per batch element.
//   k = (r<<5)|lane :  r = in-register bit 5..9 stages (pure FMA),
//                      lane = shfl_xor stages (bits 0..4).
//   No shared memory, no __syncthreads in the main kernel.
// ---------------------------------------------------------------------------

#define NQ 10
#define NT 256          // 8 warps = 8 batch elements per block

__device__ int    g_flag;          // inputs.max() > 1 ?
__device__ float2 g_gate[NQ][4];   // Rx(wx*2pi) @ Rz(wz*2pi) per qubit
__device__ float  g_costh, g_sinth;

__global__ void k_reset() { g_flag = 0; }

__global__ void k_flag(const float* __restrict__ in, int n) {
    int i = blockIdx.x * blockDim.x + threadIdx.x;
    int stride = gridDim.x * blockDim.x;
    int p = 0;
    for (; i < n; i += stride) p |= (in[i] > 1.0f);
    if (__syncthreads_or(p)) {
        if (threadIdx.x == 0) atomicOr(&g_flag, 1);
    }
}

__global__ void k_gates(const float* __restrict__ w) {
    int q = threadIdx.x;
    if (q < NQ) {
        float sx, cx, sz, cz;
        sincospif(w[3 + q], &sx, &cx);        // Rx half-angle = pi*w
        sincospif(w[3 + NQ + q], &sz, &cz);   // Rz half-angle = pi*w
        // G = Rx @ Rz
        g_gate[q][0] = make_float2( cx * cz, -cx * sz);
        g_gate[q][1] = make_float2( sx * sz, -sx * cz);
        g_gate[q][2] = make_float2(-sx * sz, -sx * cz);
        g_gate[q][3] = make_float2( cx * cz,  cx * sz);
    }
    if (q == 0) {
        float s, c;
        sincospif(2.0f * (w[0] + w[1] + w[2]), &s, &c); // theta = 2pi*sum(w)
        g_costh = c; g_sinth = s;
    }
}

__device__ __forceinline__ float2 cmad2(float2 Ga, float2 a, float2 Gb, float2 c) {
    float2 o;
    o.x = Ga.x * a.x - Ga.y * a.y + Gb.x * c.x - Gb.y * c.y;
    o.y = Ga.x * a.y + Ga.y * a.x + Gb.x * c.y + Gb.y * c.x;
    return o;
}

__global__ __launch_bounds__(NT) void k_main(const float* __restrict__ in,
                                             float* __restrict__ out,
                                             int batch) {
    const int warp = threadIdx.x >> 5;
    const int lane = threadIdx.x & 31;
    const int b = blockIdx.x * (NT / 32) + warp;
    if (b >= batch) return;
    const int flag = g_flag;

    // --- load the 10 features (broadcast reads, all L1 hits) ---
    float x[NQ];
    #pragma unroll
    for (int q = 0; q < NQ; q++) {
        float v = __ldg(&in[b * NQ + q]);
        x[q] = flag ? atanf(v) : v;
    }
    float Q = 0.0f;
    #pragma unroll
    for (int q = 0; q < NQ; q++) Q += x[q] * x[q];

    // --- per-lane subset sums in butterfly (Gray-coded) layout ---
    // state index s bit i (LSB=0) <-> qubit 9-i; sign = +1 if bit set.
    const int gl = lane ^ (lane >> 1);          // gray(lane)
    float Lbase = 0.0f, Hmine = 0.0f;
    #pragma unroll
    for (int i = 0; i < 5; i++) {
        Lbase += ((gl >> i) & 1) ? x[9 - i] : -x[9 - i];  // qubits 9..5
        Hmine += ((gl >> i) & 1) ? x[4 - i] : -x[4 - i];  // qubits 4..0
    }
    // flipping slo bit 4 toggles the x[5] term
    const float Lflip = Lbase - 2.0f * (((gl >> 4) & 1) ? x[5] : -x[5]);

    // --- build state amp[r] at butterfly slot p=(r<<5)|lane, s = p^(p>>1) ---
    float2 amp[32];
    #pragma unroll
    for (int r = 0; r < 32; r++) {
        float H = __shfl_sync(0xFFFFFFFFu, Hmine, r);    // H[gray(r)]
        float S = H + ((r & 1) ? Lflip : Lbase);
        float A = S + 0.5f * (S * S - Q);
        float sn, cs;
        sincospif(A, &sn, &cs);
        amp[r] = make_float2(cs * 0.03125f, sn * 0.03125f);
    }

    // --- qubits 0..4: register-bit butterflies (distance 512..32) ---
    #pragma unroll
    for (int q = 0; q < 5; q++) {
        const int dr = 1 << (4 - q);
        const float2 G00 = g_gate[q][0];
        const float2 G01 = g_gate[q][1];
        const float2 G10 = g_gate[q][2];
        const float2 G11 = g_gate[q][3];
        #pragma unroll
        for (int i = 0; i < 16; i++) {
            int r = ((i & ~(dr - 1)) << 1) | (i & (dr - 1));
            float2 a = amp[r];
            float2 c = amp[r + dr];
            amp[r]      = cmad2(G00, a, G01, c);
            amp[r + dr] = cmad2(G10, a, G11, c);
        }
    }

    // --- qubits 5..9: lane-bit butterflies via shfl_xor (distance 16..1) ---
    #pragma unroll
    for (int q = 5; q < 10; q++) {
        const int m = 1 << (9 - q);
        const int bit = (lane >> (9 - q)) & 1;
        const float2 Ga = bit ? g_gate[q][3] : g_gate[q][0]; // coeff of mine
        const float2 Gb = bit ? g_gate[q][2] : g_gate[q][1]; // coeff of other
        #pragma unroll
        for (int r = 0; r < 32; r++) {
            float2 o;
            o.x = __shfl_xor_sync(0xFFFFFFFFu, amp[r].x, m);
            o.y = __shfl_xor_sync(0xFFFFFFFFu, amp[r].y, m);
            amp[r] = cmad2(Ga, amp[r], Gb, o);
        }
    }

    // --- output: pairs (k, k^768); 768 flips register bits 3,4 only ---
    const float cth  = g_costh;
    const float sth2 = 2.0f * g_sinth;
    float acc = 0.0f;
    #pragma unroll
    for (int r = 0; r < 16; r++) {              // bit4 of r == 0  =>  k bit9 == 0
        float2 w0 = amp[r];
        float2 w1 = amp[r ^ 24];
        acc += cth  * ((w1.x * w1.x + w1.y * w1.y) - (w0.x * w0.x + w0.y * w0.y))
             + sth2 * (w0.x * w1.x + w0.y * w1.y);
    }
    #pragma unroll
    for (int o = 16; o; o >>= 1) acc += __shfl_xor_sync(0xFFFFFFFFu, acc, o);
    if (lane == 0) out[b] = acc;
}

extern "C" void kernel_launch(void* const* d_in, const int* in_sizes, int n_in,
                              void* d_out, int out_size) {
    const float* inputs = (const float*)d_in[0];   // [8192, 10]
    const float* weight = (const float*)d_in[1];   // [23]
    // d_in[2] = entangle_matrix: fixed CNOT cascade, replaced by closed-form perm
    float* out = (float*)d_out;                    // [8192]

    const int batch = in_sizes[0] / NQ;
    const int n_elems = in_sizes[0];

    k_reset<<<1, 1>>>();
    k_flag<<<160, 512>>>(inputs, n_elems);
    k_gates<<<1, 32>>>(weight);
    k_main<<<(batch + (NT / 32) - 1) / (NT / 32), NT>>>(inputs, out, batch);
}

// round 3
// speedup vs baseline: 2.3318x; 1.3381x over previous
#include <cuda_runtime.h>
#include <math.h>

// ---------------------------------------------------------------------------
// Quantum circuit collapsed analytically:
//   amp(b,s)  = (1/32) * exp(i*pi*A),  A = S + (S^2 - Q)/2
//   M = E R E ; R = tensor (Rx_q Rz_q). Rz is diagonal -> folded into the
//   initial phase: A(p) += Z(p) = sum_q (+-) w_z[q] over plain bits of slot p.
//   Stages apply Rx only: w = c*mine + s*J(other), J(x,y) = (y,-x).
//   out(b) = cos(th)*(P1-P0) + 2 sin(th)*Re<x0,x1> over pairs (r, r^24).
//
// One warp per batch element; full 1024-amp state in registers.
// ---------------------------------------------------------------------------

#define NQ 10
#define NT 256          // 8 warps = 8 batch elements per block

__device__ int    g_flag;         // inputs.max() > 1 ?
__device__ float2 g_rx[NQ];       // (cos(pi*wx), sin(pi*wx)) per qubit
__device__ float  g_wz[NQ];       // raw Rz weights (units of pi)
__device__ float  g_costh, g_sinth;

__global__ void k_prep(const float* __restrict__ w) {
    int q = threadIdx.x;
    if (q == 0) g_flag = 0;
    if (q < NQ) {
        float sx, cx;
        sincospif(w[3 + q], &sx, &cx);    // Rx half-angle = pi*wx
        g_rx[q] = make_float2(cx, sx);
        g_wz[q] = w[3 + NQ + q];
    }
    if (q == 0) {
        float s, c;
        sincospif(2.0f * (w[0] + w[1] + w[2]), &s, &c); // theta = 2pi*sum(w)
        g_costh = c; g_sinth = s;
    }
}

__global__ void k_flag(const float* __restrict__ in, int n) {
    int i = blockIdx.x * blockDim.x + threadIdx.x;
    int stride = gridDim.x * blockDim.x;
    int p = 0;
    for (; i < n; i += stride) p |= (in[i] > 1.0f);
    if (__syncthreads_or(p)) {
        if (threadIdx.x == 0) atomicOr(&g_flag, 1);
    }
}

__global__ __launch_bounds__(NT) void k_main(const float* __restrict__ in,
                                             float* __restrict__ out,
                                             int batch) {
    const int warp = threadIdx.x >> 5;
    const int lane = threadIdx.x & 31;
    const int b = blockIdx.x * (NT / 32) + warp;
    if (b >= batch) return;
    const int flag = g_flag;

    // --- load the 10 features ---
    float x[NQ];
    #pragma unroll
    for (int q = 0; q < NQ; q++) {
        float v = __ldg(&in[b * NQ + q]);
        x[q] = flag ? atanf(v) : v;
    }
    float Q = 0.0f;
    #pragma unroll
    for (int q = 0; q < NQ; q++) Q += x[q] * x[q];

    // --- per-lane subset sums ---
    // slot p = (r<<5)|lane ; original state s = gray(p) ; s bit i <-> qubit 9-i.
    const int gl = lane ^ (lane >> 1);          // gray of low 5 bits of p
    float Lbase = 0.0f, Hmine = 0.0f;
    float Zlo = 0.0f, Zhm = 0.0f;
    #pragma unroll
    for (int i = 0; i < 5; i++) {
        Lbase += ((gl >> i) & 1)   ? x[9 - i] : -x[9 - i];       // S low (gray)
        Hmine += ((gl >> i) & 1)   ? x[4 - i] : -x[4 - i];       // S high (gray)
        Zlo   += ((lane >> i) & 1) ? g_wz[9 - i] : -g_wz[9 - i]; // Rz low (plain)
        Zhm   += ((lane >> i) & 1) ? g_wz[4 - i] : -g_wz[4 - i]; // Rz high (plain)
    }
    // s bit 4 = p4 ^ p5 : toggle x[5] term when r is odd
    const float Lflip = Lbase - 2.0f * (((gl >> 4) & 1) ? x[5] : -x[5]);
    const float dlane = Zlo - 0.5f * Q;

    // --- build state: amp[r] at slot p=(r<<5)|lane, phase includes all Rz ---
    float2 amp[32];
    #pragma unroll
    for (int r = 0; r < 32; r++) {
        float H  = __shfl_sync(0xFFFFFFFFu, Hmine, r);   // S_high[gray(r)]
        float Zh = __shfl_sync(0xFFFFFFFFu, Zhm, r);     // Z_high[r]
        float S  = H + ((r & 1) ? Lflip : Lbase);
        float A  = fmaf(0.5f * S, S, S) + (dlane + Zh);
        float sn, cs;
        sincospif(A, &sn, &cs);
        amp[r] = make_float2(cs * 0.03125f, sn * 0.03125f);
    }

    // --- qubits 0..4: register-bit Rx butterflies (p bits 9..5) ---
    #pragma unroll
    for (int q = 0; q < 5; q++) {
        const int dr = 1 << (4 - q);
        const float c = g_rx[q].x;
        const float s = g_rx[q].y;
        #pragma unroll
        for (int i = 0; i < 16; i++) {
            int k = ((i & ~(dr - 1)) << 1) | (i & (dr - 1));
            float2 a  = amp[k];
            float2 cc = amp[k + dr];
            amp[k].x      = fmaf(c, a.x,   s * cc.y);
            amp[k].y      = fmaf(c, a.y,  -s * cc.x);
            amp[k + dr].x = fmaf(c, cc.x,  s * a.y);
            amp[k + dr].y = fmaf(c, cc.y, -s * a.x);
        }
    }

    // --- qubits 5..9: lane-bit Rx butterflies via shfl_xor (p bits 4..0) ---
    // Uniform across lanes: new = c*mine + s*J(other), J(x,y)=(y,-x).
    #pragma unroll
    for (int q = 5; q < 10; q++) {
        const int m = 1 << (9 - q);
        const float c = g_rx[q].x;
        const float s = g_rx[q].y;
        #pragma unroll
        for (int r = 0; r < 32; r++) {
            float ox = __shfl_xor_sync(0xFFFFFFFFu, amp[r].x, m);
            float oy = __shfl_xor_sync(0xFFFFFFFFu, amp[r].y, m);
            amp[r].x = fmaf(c, amp[r].x,  s * oy);
            amp[r].y = fmaf(c, amp[r].y, -s * ox);
        }
    }

    // --- output: pairs (k, k^768); 768 flips register bits 3,4 only ---
    const float cth  = g_costh;
    const float sth2 = 2.0f * g_sinth;
    float acc = 0.0f;
    #pragma unroll
    for (int r = 0; r < 16; r++) {              // bit4 of r == 0  =>  k bit9 == 0
        float2 w0 = amp[r];
        float2 w1 = amp[r ^ 24];
        acc += cth  * ((w1.x * w1.x + w1.y * w1.y) - (w0.x * w0.x + w0.y * w0.y))
             + sth2 * (w0.x * w1.x + w0.y * w1.y);
    }
    #pragma unroll
    for (int o = 16; o; o >>= 1) acc += __shfl_xor_sync(0xFFFFFFFFu, acc, o);
    if (lane == 0) out[b] = acc;
}

extern "C" void kernel_launch(void* const* d_in, const int* in_sizes, int n_in,
                              void* d_out, int out_size) {
    const float* inputs = (const float*)d_in[0];   // [8192, 10]
    const float* weight = (const float*)d_in[1];   // [23]
    // d_in[2] = entangle_matrix: fixed CNOT cascade, replaced by closed-form perm
    float* out = (float*)d_out;                    // [8192]

    const int batch = in_sizes[0] / NQ;
    const int n_elems = in_sizes[0];

    k_prep<<<1, 32>>>(weight);
    k_flag<<<160, 512>>>(inputs, n_elems);
    k_main<<<(batch + (NT / 32) - 1) / (NT / 32), NT>>>(inputs, out, batch);
}

// round 4
// speedup vs baseline: 2.6325x; 1.1289x over previous
#include <cuda_runtime.h>
#include <math.h>

// ---------------------------------------------------------------------------
// Quantum circuit collapsed analytically (see R1-R3):
//   amp(b,s) = (1/32) exp(i*pi*A),  A = S + (S^2-Q)/2 + Z(p)   (Rz folded in)
//   butterfly stages apply Rx only:  X += s*Y_partner, Y -= s*X_partner
//   out(b) = [cth*(P1-P0) + 2*sth*Re<x0,x1>] / 1024  over pairs (r, r^24)
//
// R4: amplitudes packed two-per-register (f32x2 PTX ops), one warp per batch
// element, single-kernel prologue.
// ---------------------------------------------------------------------------

#define NQ 10
#define NT 256          // 8 warps = 8 batch elements per block
typedef unsigned long long u64;

#define F2PACK(d, lo, hi) asm("mov.b64 %0, {%1, %2};" : "=l"(d) : "f"(lo), "f"(hi))
#define F2UNPACK(lo, hi, s) asm("mov.b64 {%0, %1}, %2;" : "=f"(lo), "=f"(hi) : "l"(s))
#define F2FMA(d, a, b, c) asm("fma.rn.f32x2 %0, %1, %2, %3;" : "=l"(d) : "l"(a), "l"(b), "l"(c))
#define F2MUL(d, a, b)    asm("mul.rn.f32x2 %0, %1, %2;"     : "=l"(d) : "l"(a), "l"(b))

__device__ __forceinline__ u64 f2bcast(float v) { u64 d; F2PACK(d, v, v); return d; }
__device__ __forceinline__ u64 f2fma(u64 a, u64 b, u64 c) { u64 d; F2FMA(d, a, b, c); return d; }
__device__ __forceinline__ u64 f2mul(u64 a, u64 b) { u64 d; F2MUL(d, a, b); return d; }

__device__ int    g_flag;         // inputs.max() > 1 ?
__device__ float2 g_rx[NQ];       // (cos(pi*wx), sin(pi*wx)) per qubit
__device__ float  g_wz[NQ];       // raw Rz weights (units of pi)
__device__ float  g_costh, g_sinth;

// Single prologue: flag scan (1 block, no reset/atomics needed) + gate prep.
__global__ __launch_bounds__(1024) void k_pre(const float* __restrict__ in, int n,
                                              const float* __restrict__ w) {
    int t = threadIdx.x;
    int p = 0;
    int n4 = n >> 2;
    const float4* in4 = (const float4*)in;
    for (int i = t; i < n4; i += 1024) {
        float4 v = in4[i];
        p |= (v.x > 1.0f) | (v.y > 1.0f) | (v.z > 1.0f) | (v.w > 1.0f);
    }
    for (int i = (n4 << 2) + t; i < n; i += 1024) p |= (in[i] > 1.0f);
    int f = __syncthreads_or(p);
    if (t == 0) g_flag = f;
    if (t < NQ) {
        float sx, cx;
        sincospif(w[3 + t], &sx, &cx);        // Rx half-angle = pi*wx
        g_rx[t] = make_float2(cx, sx);
        g_wz[t] = w[3 + NQ + t];
    }
    if (t == 0) {
        float s, c;
        sincospif(2.0f * (w[0] + w[1] + w[2]), &s, &c); // theta = 2pi*sum(w)
        g_costh = c; g_sinth = s;
    }
}

__global__ __launch_bounds__(NT) void k_main(const float* __restrict__ in,
                                             float* __restrict__ out,
                                             int batch) {
    const int warp = threadIdx.x >> 5;
    const int lane = threadIdx.x & 31;
    const int b = blockIdx.x * (NT / 32) + warp;
    if (b >= batch) return;
    const int flag = g_flag;

    // --- load the 10 features ---
    float x[NQ];
    #pragma unroll
    for (int q = 0; q < NQ; q++) {
        float v = __ldg(&in[b * NQ + q]);
        x[q] = flag ? atanf(v) : v;
    }
    float Q = 0.0f;
    #pragma unroll
    for (int q = 0; q < NQ; q++) Q += x[q] * x[q];

    // --- per-lane subset sums ---
    // slot p = (r<<5)|lane ; original state s = gray(p) ; s bit i <-> qubit 9-i.
    const int gl = lane ^ (lane >> 1);
    float Lbase = 0.0f, Hmine = 0.0f, Zlo = 0.0f, Zhm = 0.0f;
    #pragma unroll
    for (int i = 0; i < 5; i++) {
        Lbase += ((gl >> i) & 1)   ? x[9 - i] : -x[9 - i];       // S low (gray)
        Hmine += ((gl >> i) & 1)   ? x[4 - i] : -x[4 - i];       // S high (gray)
        Zlo   += ((lane >> i) & 1) ? g_wz[9 - i] : -g_wz[9 - i]; // Rz low (plain)
        Zhm   += ((lane >> i) & 1) ? g_wz[4 - i] : -g_wz[4 - i]; // Rz high (plain)
    }
    const float Lflip = Lbase - 2.0f * (((gl >> 4) & 1) ? x[5] : -x[5]);
    const float dlane = Zlo - 0.5f * Q;

    // --- build state, packed over r-bit0: X2[t]=(x_{2t},x_{2t+1}), t=r>>1 ---
    u64 X2[16], Y2[16];
    #pragma unroll
    for (int t = 0; t < 16; t++) {
        int r0 = 2 * t, r1 = 2 * t + 1;
        float H0  = __shfl_sync(0xFFFFFFFFu, Hmine, r0);
        float Zh0 = __shfl_sync(0xFFFFFFFFu, Zhm,  r0);
        float H1  = __shfl_sync(0xFFFFFFFFu, Hmine, r1);
        float Zh1 = __shfl_sync(0xFFFFFFFFu, Zhm,  r1);
        float S0 = H0 + Lbase;
        float S1 = H1 + Lflip;
        float A0 = fmaf(0.5f * S0, S0, S0) + (dlane + Zh0);
        float A1 = fmaf(0.5f * S1, S1, S1) + (dlane + Zh1);
        float sn0, cs0, sn1, cs1;
        sincospif(A0, &sn0, &cs0);
        sincospif(A1, &sn1, &cs1);
        F2PACK(X2[t], cs0, cs1);
        F2PACK(Y2[t], sn0, sn1);
    }

    // --- qubits 0..3: packed register-bit butterflies (t bits 3..0) ---
    #pragma unroll
    for (int q = 0; q < 4; q++) {
        const int dt = 8 >> q;
        const u64 c2  = f2bcast(g_rx[q].x);
        const u64 s2  = f2bcast(g_rx[q].y);
        const u64 ns2 = f2bcast(-g_rx[q].y);
        #pragma unroll
        for (int i = 0; i < 8; i++) {
            int k = ((i & ~(dt - 1)) << 1) | (i & (dt - 1));
            u64 xa = X2[k], ya = Y2[k], xb = X2[k + dt], yb = Y2[k + dt];
            X2[k]      = f2fma(c2, xa, f2mul(s2,  yb));
            Y2[k]      = f2fma(c2, ya, f2mul(ns2, xb));
            X2[k + dt] = f2fma(c2, xb, f2mul(s2,  ya));
            Y2[k + dt] = f2fma(c2, yb, f2mul(ns2, xa));
        }
    }

    // --- qubit 4: within-pack butterfly (r bit0), scalar halves ---
    {
        const float c = g_rx[4].x, s = g_rx[4].y;
        #pragma unroll
        for (int t = 0; t < 16; t++) {
            float xl, xh, yl, yh;
            F2UNPACK(xl, xh, X2[t]);
            F2UNPACK(yl, yh, Y2[t]);
            float nxl = fmaf(c, xl,  s * yh);
            float nxh = fmaf(c, xh,  s * yl);
            float nyl = fmaf(c, yl, -s * xh);
            float nyh = fmaf(c, yh, -s * xl);
            F2PACK(X2[t], nxl, nxh);
            F2PACK(Y2[t], nyl, nyh);
        }
    }

    // --- qubits 5..9: lane-bit butterflies via 64-bit shfl_xor ---
    #pragma unroll
    for (int q = 5; q < 10; q++) {
        const int m = 1 << (9 - q);
        const u64 c2  = f2bcast(g_rx[q].x);
        const u64 s2  = f2bcast(g_rx[q].y);
        const u64 ns2 = f2bcast(-g_rx[q].y);
        #pragma unroll
        for (int t = 0; t < 16; t++) {
            u64 oy = __shfl_xor_sync(0xFFFFFFFFu, Y2[t], m);
            u64 ox = __shfl_xor_sync(0xFFFFFFFFu, X2[t], m);
            X2[t] = f2fma(c2, X2[t], f2mul(s2,  oy));
            Y2[t] = f2fma(c2, Y2[t], f2mul(ns2, ox));
        }
    }

    // --- output: pairs (r, r^24) -> packed (t, t^12), t = 0..7 ---
    const u64 cth2  = f2bcast(g_costh);
    const u64 ncth2 = f2bcast(-g_costh);
    const u64 st2   = f2bcast(2.0f * g_sinth);
    u64 acc2 = f2bcast(0.0f);
    #pragma unroll
    for (int t = 0; t < 8; t++) {
        int u = t ^ 12;
        u64 p1 = f2fma(X2[u], X2[u], f2mul(Y2[u], Y2[u]));   // |w1|^2
        u64 p0 = f2fma(X2[t], X2[t], f2mul(Y2[t], Y2[t]));   // |w0|^2
        u64 dt = f2fma(X2[t], X2[u], f2mul(Y2[t], Y2[u]));   // Re<w0,w1>
        acc2 = f2fma(cth2,  p1, acc2);
        acc2 = f2fma(ncth2, p0, acc2);
        acc2 = f2fma(st2,   dt, acc2);
    }
    float alo, ahi;
    F2UNPACK(alo, ahi, acc2);
    float acc = alo + ahi;
    #pragma unroll
    for (int o = 16; o; o >>= 1) acc += __shfl_xor_sync(0xFFFFFFFFu, acc, o);
    if (lane == 0) out[b] = acc * (1.0f / 1024.0f);
}

extern "C" void kernel_launch(void* const* d_in, const int* in_sizes, int n_in,
                              void* d_out, int out_size) {
    const float* inputs = (const float*)d_in[0];   // [8192, 10]
    const float* weight = (const float*)d_in[1];   // [23]
    // d_in[2] = entangle_matrix: fixed CNOT cascade, replaced by closed-form perm
    float* out = (float*)d_out;                    // [8192]

    const int batch = in_sizes[0] / NQ;
    const int n_elems = in_sizes[0];

    k_pre<<<1, 1024>>>(inputs, n_elems, weight);
    k_main<<<(batch + (NT / 32) - 1) / (NT / 32), NT>>>(inputs, out, batch);
}

// round 5
// speedup vs baseline: 2.6352x; 1.0010x over previous
#include <cuda_runtime.h>
#include <math.h>

// ---------------------------------------------------------------------------
// Quantum circuit collapsed analytically (see R1-R4):
//   amp(b,s) = (1/32) exp(i*pi*A),  A = S + (S^2-Q)/2 + Z(p)   (Rz folded in)
//   Rx butterflies in tangent form: out = a + t*b, global scale C = prod(c_q)
//   folded (as C^2) into the output coefficients.
//   out(b) = ccoef*(P1-P0) + scoef*Re<x0,x1> over pairs (r, r^24)
//
// R5: tangent butterflies (1 FMA per rotation), atan/Q precomputed per batch
// row, weight-side subset sums precomputed per lane.
// ---------------------------------------------------------------------------

#define NQ 10
#define NT 256          // 8 warps = 8 batch elements per block
#define MAXB 8192
typedef unsigned long long u64;

#define F2PACK(d, lo, hi) asm("mov.b64 %0, {%1, %2};" : "=l"(d) : "f"(lo), "f"(hi))
#define F2UNPACK(lo, hi, s) asm("mov.b64 {%0, %1}, %2;" : "=f"(lo), "=f"(hi) : "l"(s))
#define F2FMA(d, a, b, c) asm("fma.rn.f32x2 %0, %1, %2, %3;" : "=l"(d) : "l"(a), "l"(b), "l"(c))
#define F2MUL(d, a, b)    asm("mul.rn.f32x2 %0, %1, %2;"     : "=l"(d) : "l"(a), "l"(b))

__device__ __forceinline__ u64 f2bcast(float v) { u64 d; F2PACK(d, v, v); return d; }
__device__ __forceinline__ u64 f2fma(u64 a, u64 b, u64 c) { u64 d; F2FMA(d, a, b, c); return d; }
__device__ __forceinline__ u64 f2mul(u64 a, u64 b) { u64 d; F2MUL(d, a, b); return d; }

__device__ int   g_flag;
__device__ float g_t[NQ];         // tan(pi*wx) per qubit
__device__ float g_ccoef, g_scoef;// output coefs incl. C^2/1024
__device__ float g_zlo[32], g_zhm[32];   // Rz subset sums per lane
__device__ float g_xt[MAXB * NQ]; // atan-transformed inputs
__device__ float g_q[MAXB];       // per-row sum of squares

__global__ void k_prep(const float* __restrict__ w) {
    int t = threadIdx.x;
    if (t == 0) {
        g_flag = 0;
        float csq = 1.0f;
        #pragma unroll
        for (int q = 0; q < NQ; q++) {
            float sx, cx;
            sincospif(w[3 + q], &sx, &cx);     // Rx half-angle = pi*wx
            g_t[q] = sx / cx;
            csq *= cx * cx;
        }
        float s, c;
        sincospif(2.0f * (w[0] + w[1] + w[2]), &s, &c); // theta = 2pi*sum(w)
        const float k = csq * (1.0f / 1024.0f);
        g_ccoef = c * k;
        g_scoef = 2.0f * s * k;
    }
    if (t < 32) {
        float zlo = 0.0f, zhm = 0.0f;
        #pragma unroll
        for (int i = 0; i < 5; i++) {
            float wl = w[3 + NQ + 9 - i];     // qubits 9..5 (p bits 0..4)
            float wh = w[3 + NQ + 4 - i];     // qubits 4..0 (p bits 5..9)
            zlo += ((t >> i) & 1) ? wl : -wl;
            zhm += ((t >> i) & 1) ? wh : -wh;
        }
        g_zlo[t] = zlo;
        g_zhm[t] = zhm;
    }
}

__global__ void k_flag(const float* __restrict__ in, int n) {
    int i = blockIdx.x * blockDim.x + threadIdx.x;
    int stride = gridDim.x * blockDim.x;
    int p = 0;
    for (; i < n; i += stride) p |= (in[i] > 1.0f);
    if (__syncthreads_or(p)) {
        if (threadIdx.x == 0) atomicOr(&g_flag, 1);
    }
}

__global__ void k_xt(const float* __restrict__ in, int batch) {
    int b = blockIdx.x * blockDim.x + threadIdx.x;
    if (b >= batch) return;
    const int flag = g_flag;
    float q = 0.0f;
    #pragma unroll
    for (int j = 0; j < NQ; j++) {
        float v = in[b * NQ + j];
        if (flag) v = atanf(v);
        g_xt[b * NQ + j] = v;
        q += v * v;
    }
    g_q[b] = q;
}

__global__ __launch_bounds__(NT) void k_main(float* __restrict__ out, int batch) {
    const int warp = threadIdx.x >> 5;
    const int lane = threadIdx.x & 31;
    const int b = blockIdx.x * (NT / 32) + warp;
    if (b >= batch) return;

    // --- load precomputed features ---
    float x[NQ];
    #pragma unroll
    for (int q = 0; q < NQ; q++) x[q] = __ldg(&g_xt[b * NQ + q]);
    const float Q = __ldg(&g_q[b]);

    // --- per-lane subset sums (data side); weight side from tables ---
    // slot p = (r<<5)|lane ; state s = gray(p) ; s bit i <-> qubit 9-i.
    const int gl = lane ^ (lane >> 1);
    float Lbase = 0.0f, Hmine = 0.0f;
    #pragma unroll
    for (int i = 0; i < 5; i++) {
        Lbase += ((gl >> i) & 1) ? x[9 - i] : -x[9 - i];
        Hmine += ((gl >> i) & 1) ? x[4 - i] : -x[4 - i];
    }
    const float Lflip = Lbase - 2.0f * (((gl >> 4) & 1) ? x[5] : -x[5]);
    const float Zhm   = g_zhm[lane];
    const float dlane = fmaf(-0.5f, Q, g_zlo[lane]);

    // --- build state packed over r-bit0: X2[t]=(x_{2t},x_{2t+1}) ---
    u64 X2[16], Y2[16];
    #pragma unroll
    for (int t = 0; t < 16; t++) {
        int r0 = 2 * t, r1 = 2 * t + 1;
        float H0  = __shfl_sync(0xFFFFFFFFu, Hmine, r0);
        float Zh0 = __shfl_sync(0xFFFFFFFFu, Zhm,  r0);
        float H1  = __shfl_sync(0xFFFFFFFFu, Hmine, r1);
        float Zh1 = __shfl_sync(0xFFFFFFFFu, Zhm,  r1);
        float S0 = H0 + Lbase;
        float S1 = H1 + Lflip;
        float A0 = fmaf(0.5f * S0, S0, S0) + (dlane + Zh0);
        float A1 = fmaf(0.5f * S1, S1, S1) + (dlane + Zh1);
        float sn0, cs0, sn1, cs1;
        sincospif(A0, &sn0, &cs0);
        sincospif(A1, &sn1, &cs1);
        F2PACK(X2[t], cs0, cs1);
        F2PACK(Y2[t], sn0, sn1);
    }

    // --- qubits 0..3: packed register-bit butterflies (tangent form) ---
    #pragma unroll
    for (int q = 0; q < 4; q++) {
        const int dt = 8 >> q;
        const u64 t2  = f2bcast(g_t[q]);
        const u64 nt2 = f2bcast(-g_t[q]);
        #pragma unroll
        for (int i = 0; i < 8; i++) {
            int k = ((i & ~(dt - 1)) << 1) | (i & (dt - 1));
            u64 xa = X2[k], ya = Y2[k], xb = X2[k + dt], yb = Y2[k + dt];
            X2[k]      = f2fma(t2,  yb, xa);
            Y2[k]      = f2fma(nt2, xb, ya);
            X2[k + dt] = f2fma(t2,  ya, xb);
            Y2[k + dt] = f2fma(nt2, xa, yb);
        }
    }

    // --- qubit 4: within-pack butterfly (tangent form) ---
    {
        const float t = g_t[4];
        #pragma unroll
        for (int k = 0; k < 16; k++) {
            float xl, xh, yl, yh;
            F2UNPACK(xl, xh, X2[k]);
            F2UNPACK(yl, yh, Y2[k]);
            float nxl = fmaf( t, yh, xl);
            float nxh = fmaf( t, yl, xh);
            float nyl = fmaf(-t, xh, yl);
            float nyh = fmaf(-t, xl, yh);
            F2PACK(X2[k], nxl, nxh);
            F2PACK(Y2[k], nyl, nyh);
        }
    }

    // --- qubits 5..9: lane-bit butterflies via 64-bit shfl_xor (tangent) ---
    #pragma unroll
    for (int q = 5; q < 10; q++) {
        const int m = 1 << (9 - q);
        const u64 t2  = f2bcast(g_t[q]);
        const u64 nt2 = f2bcast(-g_t[q]);
        #pragma unroll
        for (int k = 0; k < 16; k++) {
            u64 oy = __shfl_xor_sync(0xFFFFFFFFu, Y2[k], m);
            u64 ox = __shfl_xor_sync(0xFFFFFFFFu, X2[k], m);
            X2[k] = f2fma(t2,  oy, X2[k]);
            Y2[k] = f2fma(nt2, ox, Y2[k]);
        }
    }

    // --- output: pairs (r, r^24) -> packed (t, t^12); coefs pre-scaled ---
    const u64 cc  = f2bcast(g_ccoef);
    const u64 ncc = f2bcast(-g_ccoef);
    const u64 sc  = f2bcast(g_scoef);
    u64 acc2 = f2bcast(0.0f);
    #pragma unroll
    for (int t = 0; t < 8; t++) {
        int u = t ^ 12;
        u64 p1 = f2fma(X2[u], X2[u], f2mul(Y2[u], Y2[u]));   // |w1|^2
        u64 p0 = f2fma(X2[t], X2[t], f2mul(Y2[t], Y2[t]));   // |w0|^2
        u64 dt = f2fma(X2[t], X2[u], f2mul(Y2[t], Y2[u]));   // Re<w0,w1>
        acc2 = f2fma(cc,  p1, acc2);
        acc2 = f2fma(ncc, p0, acc2);
        acc2 = f2fma(sc,  dt, acc2);
    }
    float alo, ahi;
    F2UNPACK(alo, ahi, acc2);
    float acc = alo + ahi;
    #pragma unroll
    for (int o = 16; o; o >>= 1) acc += __shfl_xor_sync(0xFFFFFFFFu, acc, o);
    if (lane == 0) out[b] = acc;
}

extern "C" void kernel_launch(void* const* d_in, const int* in_sizes, int n_in,
                              void* d_out, int out_size) {
    const float* inputs = (const float*)d_in[0];   // [8192, 10]
    const float* weight = (const float*)d_in[1];   // [23]
    // d_in[2] = entangle_matrix: fixed CNOT cascade, replaced by closed-form perm
    float* out = (float*)d_out;                    // [8192]

    const int batch = in_sizes[0] / NQ;
    const int n_elems = in_sizes[0];

    k_prep<<<1, 32>>>(weight);
    k_flag<<<160, 512>>>(inputs, n_elems);
    k_xt<<<(batch + 255) / 256, 256>>>(inputs, batch);
    k_main<<<(batch + (NT / 32) - 1) / (NT / 32), NT>>>(out, batch);
}

// round 8
// speedup vs baseline: 3.0578x; 1.1604x over previous
#include <cuda_runtime.h>
#include <math.h>

// ---------------------------------------------------------------------------
// Quantum circuit collapsed analytically (see R1-R5):
//   amp(b,s) = exp(i*pi*A)/32,  A = S + (S^2-Q)/2 + Z(p)   (Rz folded in)
//   Rx butterflies in tangent form (global scale folded into output coefs).
//   out(b) = ccoef*(P1-P0) + scoef*Re<w0,w1> over pack halves.
//
// R8: Gray-ordered register layout: reg rho holds slot r = gray(rho).
//   - E walk signs = gray(rho) bits  -> single flip at bb = ctz(rho)
//   - H walk signs = rho ^ (rho>>2)  -> flips at bits {bb, bb-1}   (R7 bugfix)
//   - register stages at compile-time masks 31(scalar),15,7,3,1(packed)
//   - output pairs = the two halves of each pack (rho ^ 16)
//   One prologue kernel (16-block flag partials + gate prep).
// ---------------------------------------------------------------------------

#define NQ 10
#define NT 256          // 8 warps = 8 batch elements per block
#define NBLK 16
typedef unsigned long long u64;

#define F2PACK(d, lo, hi) asm("mov.b64 %0, {%1, %2};" : "=l"(d) : "f"(lo), "f"(hi))
#define F2UNPACK(lo, hi, s) asm("mov.b64 {%0, %1}, %2;" : "=f"(lo), "=f"(hi) : "l"(s))
#define F2FMA(d, a, b, c) asm("fma.rn.f32x2 %0, %1, %2, %3;" : "=l"(d) : "l"(a), "l"(b), "l"(c))
#define F2MUL(d, a, b)    asm("mul.rn.f32x2 %0, %1, %2;"     : "=l"(d) : "l"(a), "l"(b))
#define F2ADD(d, a, b)    asm("add.rn.f32x2 %0, %1, %2;"     : "=l"(d) : "l"(a), "l"(b))

__device__ __forceinline__ u64 f2bcast(float v) { u64 d; F2PACK(d, v, v); return d; }
__device__ __forceinline__ u64 f2fma(u64 a, u64 b, u64 c) { u64 d; F2FMA(d, a, b, c); return d; }
__device__ __forceinline__ u64 f2mul(u64 a, u64 b) { u64 d; F2MUL(d, a, b); return d; }
__device__ __forceinline__ u64 f2add(u64 a, u64 b) { u64 d; F2ADD(d, a, b); return d; }

// compile-time-foldable count-trailing-zeros (device-safe)
__host__ __device__ __forceinline__ constexpr int ctz5(int v) {
    return (v & 1) ? 0 : (v & 2) ? 1 : (v & 4) ? 2 : (v & 8) ? 3 : 4;
}

__device__ int   g_flagv[NBLK];
__device__ float g_t[NQ];          // tan(pi*wx) per qubit
__device__ float g_ccoef, g_scoef; // output coefs incl. C^2/1024
__device__ float g_zloE[32];       // Z_low[lane] + Z_high[r=0]
__device__ float g_wzh2[5];        // 2*wz for high-qubit gray walk

// One prologue: per-block flag partials + (block 0) gate prep.
__global__ __launch_bounds__(1024) void k_pre(const float* __restrict__ in, int n,
                                              const float* __restrict__ w) {
    const int t = threadIdx.x;
    int p = 0;
    const int n4 = n >> 2;
    const float4* in4 = (const float4*)in;
    for (int i = blockIdx.x * 1024 + t; i < n4; i += NBLK * 1024) {
        float4 v = in4[i];
        p |= (v.x > 1.0f) | (v.y > 1.0f) | (v.z > 1.0f) | (v.w > 1.0f);
    }
    for (int i = (n4 << 2) + blockIdx.x * 1024 + t; i < n; i += NBLK * 1024)
        p |= (in[i] > 1.0f);
    int f = __syncthreads_or(p);
    if (t == 0) g_flagv[blockIdx.x] = f;

    if (blockIdx.x == 0) {
        if (t == 0) {
            float csq = 1.0f;
            #pragma unroll
            for (int q = 0; q < NQ; q++) {
                float sx, cx;
                sincospif(w[3 + q], &sx, &cx);      // Rx half-angle = pi*wx
                g_t[q] = sx / cx;
                csq *= cx * cx;
            }
            float s, c;
            sincospif(2.0f * (w[0] + w[1] + w[2]), &s, &c);
            const float k = csq * (1.0f / 1024.0f);
            g_ccoef = c * k;
            g_scoef = 2.0f * s * k;
            #pragma unroll
            for (int b = 0; b < 5; b++)
                g_wzh2[b] = 2.0f * w[3 + NQ + 4 - b]; // qubit 4-b <-> r-bit b
        }
        if (t < 32) {
            float zlo = 0.0f, zh0 = 0.0f;
            #pragma unroll
            for (int i = 0; i < 5; i++) {
                float wl = w[3 + NQ + 9 - i];       // qubits 9..5 (p bits 0..4)
                zlo += ((t >> i) & 1) ? wl : -wl;
                zh0 -= w[3 + NQ + i];               // Z_high at r=0: all minus
            }
            g_zloE[t] = zlo + zh0;
        }
    }
}

__global__ __launch_bounds__(NT) void k_main(const float* __restrict__ in,
                                             float* __restrict__ out, int batch) {
    const int warp = threadIdx.x >> 5;
    const int lane = threadIdx.x & 31;
    const int b = blockIdx.x * (NT / 32) + warp;
    if (b >= batch) return;

    // --- flag from per-block partials ---
    int fp = (lane < NBLK) ? g_flagv[lane] : 0;
    const int flag = __any_sync(0xFFFFFFFFu, fp != 0);

    // --- load + transform features ---
    float x[NQ];
    #pragma unroll
    for (int q = 0; q < NQ; q++) x[q] = __ldg(&in[b * NQ + q]);
    if (flag) {
        #pragma unroll
        for (int q = 0; q < NQ; q++) x[q] = atanf(x[q]);
    }
    float Q = 0.0f;
    #pragma unroll
    for (int q = 0; q < NQ; q++) Q += x[q] * x[q];

    // --- lane-side terms ---
    const int gl = lane ^ (lane >> 1);
    float Lbase = 0.0f;
    #pragma unroll
    for (int i = 0; i < 5; i++)
        Lbase += ((gl >> i) & 1) ? x[9 - i] : -x[9 - i];
    const float Lflip = Lbase - 2.0f * (((gl >> 4) & 1) ? x[5] : -x[5]);
    const float E0 = fmaf(-0.5f, Q, g_zloE[lane]);   // dlane + Zh[r=0]

    float wzh2[5], xh2[5];
    #pragma unroll
    for (int i = 0; i < 5; i++) {
        wzh2[i] = g_wzh2[i];
        xh2[i]  = 2.0f * x[4 - i];                   // qubit 4-b <-> r-bit b
    }

    // --- init: scalar amps X[rho],Y[rho], slot r = gray(rho), via walks ---
    float X[32], Y[32];
    {
        float H = -(x[0] + x[1] + x[2] + x[3] + x[4]);
        float E = E0;
        #pragma unroll
        for (int rho = 0; rho < 32; rho++) {
            if (rho) {
                const int bb = ctz5(rho);                    // compile-time
                // E walk: signs = gray(rho) bits, single flip at bb
                const int eb = ((rho ^ (rho >> 1)) >> bb) & 1;
                E = eb ? (E + wzh2[bb]) : (E - wzh2[bb]);
                // H walk: signs = rho ^ (rho>>2), flips at bb and bb-1
                const int sg = rho ^ (rho >> 2);
                const int hb = (sg >> bb) & 1;
                H = hb ? (H + xh2[bb]) : (H - xh2[bb]);
                if (bb >= 1) {
                    const int hb2 = (sg >> (bb - 1)) & 1;
                    H = hb2 ? (H + xh2[bb - 1]) : (H - xh2[bb - 1]);
                }
            }
            const float L = ((rho ^ (rho >> 1)) & 1) ? Lflip : Lbase;
            float S = H + L;
            float A = fmaf(0.5f * S, S, S + E);
            sincospif(A, &Y[rho], &X[rho]);
        }
    }

    // --- qubit 0: crossed stage, storage mask 31 (scalar, pre-pack) ---
    {
        const float t0 = g_t[0];
        #pragma unroll
        for (int a = 0; a < 16; a++) {
            const int c = 31 - a;                    // a ^ 31
            float xa = X[a], ya = Y[a], xc = X[c], yc = Y[c];
            X[a] = fmaf( t0, yc, xa);
            Y[a] = fmaf(-t0, xc, ya);
            X[c] = fmaf( t0, ya, xc);
            Y[c] = fmaf(-t0, xa, yc);
        }
    }

    // --- pack over rho-bit4: X2[t] = (X[t], X[t+16]) ---
    u64 X2[16], Y2[16];
    #pragma unroll
    for (int t = 0; t < 16; t++) {
        F2PACK(X2[t], X[t], X[t + 16]);
        F2PACK(Y2[t], Y[t], Y[t + 16]);
    }

    // --- qubits 1..4: packed register stages, masks 15,7,3,1 ---
    #pragma unroll
    for (int q = 1; q < 5; q++) {
        const int i  = 4 - q;                        // r-bit index
        const int mu = (2 << i) - 1;                 // 15,7,3,1
        const u64 t2  = f2bcast(g_t[q]);
        const u64 nt2 = f2bcast(-g_t[q]);
        #pragma unroll
        for (int t = 0; t < 16; t++) {
            if (t & (1 << i)) continue;              // each pair once
            const int u = t ^ mu;
            u64 xa = X2[t], ya = Y2[t], xb = X2[u], yb = Y2[u];
            X2[t] = f2fma(t2,  yb, xa);
            Y2[t] = f2fma(nt2, xb, ya);
            X2[u] = f2fma(t2,  ya, xb);
            Y2[u] = f2fma(nt2, xa, yb);
        }
    }

    // --- qubits 5..9: lane-bit butterflies via 64-bit shfl_xor ---
    #pragma unroll
    for (int q = 5; q < 10; q++) {
        const int m = 1 << (9 - q);
        const u64 t2  = f2bcast(g_t[q]);
        const u64 nt2 = f2bcast(-g_t[q]);
        #pragma unroll
        for (int k = 0; k < 16; k++) {
            u64 oy = __shfl_xor_sync(0xFFFFFFFFu, Y2[k], m);
            u64 ox = __shfl_xor_sync(0xFFFFFFFFu, X2[k], m);
            X2[k] = f2fma(t2,  oy, X2[k]);
            Y2[k] = f2fma(nt2, ox, Y2[k]);
        }
    }

    // --- output: pairs are the two halves of each pack (mask rho^16) ---
    u64 accP = f2bcast(0.0f);
    float d = 0.0f;
    #pragma unroll
    for (int t = 0; t < 16; t++) {
        u64 P = f2fma(X2[t], X2[t], f2mul(Y2[t], Y2[t]));  // (|w0|^2, |w1|^2)
        accP = f2add(accP, P);
        float xl, xh, yl, yh;
        F2UNPACK(xl, xh, X2[t]);
        F2UNPACK(yl, yh, Y2[t]);
        d = fmaf(xl, xh, d);
        d = fmaf(yl, yh, d);
    }
    float A0, A1;
    F2UNPACK(A0, A1, accP);
    float acc = fmaf(g_ccoef, A1 - A0, g_scoef * d);
    #pragma unroll
    for (int o = 16; o; o >>= 1) acc += __shfl_xor_sync(0xFFFFFFFFu, acc, o);
    if (lane == 0) out[b] = acc;
}

extern "C" void kernel_launch(void* const* d_in, const int* in_sizes, int n_in,
                              void* d_out, int out_size) {
    const float* inputs = (const float*)d_in[0];   // [8192, 10]
    const float* weight = (const float*)d_in[1];   // [23]
    // d_in[2] = entangle_matrix: fixed CNOT cascade, replaced by closed-form perm
    float* out = (float*)d_out;                    // [8192]

    const int batch = in_sizes[0] / NQ;
    const int n_elems = in_sizes[0];

    k_pre<<<NBLK, 1024>>>(inputs, n_elems, weight);
    k_main<<<(batch + (NT / 32) - 1) / (NT / 32), NT>>>(inputs, out, batch);
}

// round 9
// speedup vs baseline: 3.5864x; 1.1729x over previous
#include <cuda_runtime.h>
#include <math.h>

// ---------------------------------------------------------------------------
// Quantum circuit collapsed analytically (see R1-R8):
//   amp(b,s) = exp(i*pi*A)/32,  A = S + (S^2-Q)/2 + Z(p)   (Rz folded in)
//   Rx butterflies in tangent form (global scale folded into output coefs).
//   out(b) = ccoef*(P1-P0) + scoef*Re<w0,w1> over pack halves.
//
// R9: exp(i*pi*A) via explicit mod-2 reduction + MUFU __sincosf
//     (moves ~450 slots/warp off the saturated fma pipe onto idle MUFU).
// Layout (R8): reg rho holds slot r = gray(rho); E walk = single flip at
// ctz(rho); H walk = flips of rho^(rho>>2); stages at masks 31,15,7,3,1;
// output pairs = pack halves (rho^16). One prologue kernel.
// ---------------------------------------------------------------------------

#define NQ 10
#define NT 256          // 8 warps = 8 batch elements per block
#define NBLK 16
typedef unsigned long long u64;

#define F2PACK(d, lo, hi) asm("mov.b64 %0, {%1, %2};" : "=l"(d) : "f"(lo), "f"(hi))
#define F2UNPACK(lo, hi, s) asm("mov.b64 {%0, %1}, %2;" : "=f"(lo), "=f"(hi) : "l"(s))
#define F2FMA(d, a, b, c) asm("fma.rn.f32x2 %0, %1, %2, %3;" : "=l"(d) : "l"(a), "l"(b), "l"(c))
#define F2MUL(d, a, b)    asm("mul.rn.f32x2 %0, %1, %2;"     : "=l"(d) : "l"(a), "l"(b))
#define F2ADD(d, a, b)    asm("add.rn.f32x2 %0, %1, %2;"     : "=l"(d) : "l"(a), "l"(b))

__device__ __forceinline__ u64 f2bcast(float v) { u64 d; F2PACK(d, v, v); return d; }
__device__ __forceinline__ u64 f2fma(u64 a, u64 b, u64 c) { u64 d; F2FMA(d, a, b, c); return d; }
__device__ __forceinline__ u64 f2mul(u64 a, u64 b) { u64 d; F2MUL(d, a, b); return d; }
__device__ __forceinline__ u64 f2add(u64 a, u64 b) { u64 d; F2ADD(d, a, b); return d; }

// compile-time-foldable count-trailing-zeros (device-safe)
__host__ __device__ __forceinline__ constexpr int ctz5(int v) {
    return (v & 1) ? 0 : (v & 2) ? 1 : (v & 4) ? 2 : (v & 8) ? 3 : 4;
}

// exp(i*pi*A): exact mod-2 reduction, then MUFU sin/cos on |arg| <= pi
__device__ __forceinline__ void sincospi_fast(float A, float* sn, float* cs) {
    float a = fmaf(-2.0f, rintf(0.5f * A), A);   // a in [-1, 1]
    __sincosf(a * 3.14159274101257324f, sn, cs); // MUFU.SIN / MUFU.COS
}

__device__ int   g_flagv[NBLK];
__device__ float g_t[NQ];          // tan(pi*wx) per qubit
__device__ float g_ccoef, g_scoef; // output coefs incl. C^2/1024
__device__ float g_zloE[32];       // Z_low[lane] + Z_high[r=0]
__device__ float g_wzh2[5];        // 2*wz for high-qubit gray walk

// One prologue: per-block flag partials + (block 0) gate prep.
__global__ __launch_bounds__(1024) void k_pre(const float* __restrict__ in, int n,
                                              const float* __restrict__ w) {
    const int t = threadIdx.x;
    int p = 0;
    const int n4 = n >> 2;
    const float4* in4 = (const float4*)in;
    for (int i = blockIdx.x * 1024 + t; i < n4; i += NBLK * 1024) {
        float4 v = in4[i];
        p |= (v.x > 1.0f) | (v.y > 1.0f) | (v.z > 1.0f) | (v.w > 1.0f);
    }
    for (int i = (n4 << 2) + blockIdx.x * 1024 + t; i < n; i += NBLK * 1024)
        p |= (in[i] > 1.0f);
    int f = __syncthreads_or(p);
    if (t == 0) g_flagv[blockIdx.x] = f;

    if (blockIdx.x == 0) {
        if (t == 0) {
            float csq = 1.0f;
            #pragma unroll
            for (int q = 0; q < NQ; q++) {
                float sx, cx;
                sincospif(w[3 + q], &sx, &cx);      // Rx half-angle = pi*wx
                g_t[q] = sx / cx;
                csq *= cx * cx;
            }
            float s, c;
            sincospif(2.0f * (w[0] + w[1] + w[2]), &s, &c);
            const float k = csq * (1.0f / 1024.0f);
            g_ccoef = c * k;
            g_scoef = 2.0f * s * k;
            #pragma unroll
            for (int b = 0; b < 5; b++)
                g_wzh2[b] = 2.0f * w[3 + NQ + 4 - b]; // qubit 4-b <-> r-bit b
        }
        if (t < 32) {
            float zlo = 0.0f, zh0 = 0.0f;
            #pragma unroll
            for (int i = 0; i < 5; i++) {
                float wl = w[3 + NQ + 9 - i];       // qubits 9..5 (p bits 0..4)
                zlo += ((t >> i) & 1) ? wl : -wl;
                zh0 -= w[3 + NQ + i];               // Z_high at r=0: all minus
            }
            g_zloE[t] = zlo + zh0;
        }
    }
}

__global__ __launch_bounds__(NT) void k_main(const float* __restrict__ in,
                                             float* __restrict__ out, int batch) {
    const int warp = threadIdx.x >> 5;
    const int lane = threadIdx.x & 31;
    const int b = blockIdx.x * (NT / 32) + warp;
    if (b >= batch) return;

    // --- flag from per-block partials ---
    int fp = (lane < NBLK) ? g_flagv[lane] : 0;
    const int flag = __any_sync(0xFFFFFFFFu, fp != 0);

    // --- load + transform features ---
    float x[NQ];
    #pragma unroll
    for (int q = 0; q < NQ; q++) x[q] = __ldg(&in[b * NQ + q]);
    if (flag) {
        #pragma unroll
        for (int q = 0; q < NQ; q++) x[q] = atanf(x[q]);
    }
    float Q = 0.0f;
    #pragma unroll
    for (int q = 0; q < NQ; q++) Q += x[q] * x[q];

    // --- lane-side terms ---
    const int gl = lane ^ (lane >> 1);
    float Lbase = 0.0f;
    #pragma unroll
    for (int i = 0; i < 5; i++)
        Lbase += ((gl >> i) & 1) ? x[9 - i] : -x[9 - i];
    const float Lflip = Lbase - 2.0f * (((gl >> 4) & 1) ? x[5] : -x[5]);
    const float E0 = fmaf(-0.5f, Q, g_zloE[lane]);   // dlane + Zh[r=0]

    float wzh2[5], xh2[5];
    #pragma unroll
    for (int i = 0; i < 5; i++) {
        wzh2[i] = g_wzh2[i];
        xh2[i]  = 2.0f * x[4 - i];                   // qubit 4-b <-> r-bit b
    }

    // --- init: scalar amps X[rho],Y[rho], slot r = gray(rho), via walks ---
    float X[32], Y[32];
    {
        float H = -(x[0] + x[1] + x[2] + x[3] + x[4]);
        float E = E0;
        #pragma unroll
        for (int rho = 0; rho < 32; rho++) {
            if (rho) {
                const int bb = ctz5(rho);                    // compile-time
                // E walk: signs = gray(rho) bits, single flip at bb
                const int eb = ((rho ^ (rho >> 1)) >> bb) & 1;
                E = eb ? (E + wzh2[bb]) : (E - wzh2[bb]);
                // H walk: signs = rho ^ (rho>>2), flips at bb and bb-1
                const int sg = rho ^ (rho >> 2);
                const int hb = (sg >> bb) & 1;
                H = hb ? (H + xh2[bb]) : (H - xh2[bb]);
                if (bb >= 1) {
                    const int hb2 = (sg >> (bb - 1)) & 1;
                    H = hb2 ? (H + xh2[bb - 1]) : (H - xh2[bb - 1]);
                }
            }
            const float L = ((rho ^ (rho >> 1)) & 1) ? Lflip : Lbase;
            float S = H + L;
            float A = fmaf(0.5f * S, S, S + E);
            sincospi_fast(A, &Y[rho], &X[rho]);
        }
    }

    // --- qubit 0: crossed stage, storage mask 31 (scalar, pre-pack) ---
    {
        const float t0 = g_t[0];
        #pragma unroll
        for (int a = 0; a < 16; a++) {
            const int c = 31 - a;                    // a ^ 31
            float xa = X[a], ya = Y[a], xc = X[c], yc = Y[c];
            X[a] = fmaf( t0, yc, xa);
            Y[a] = fmaf(-t0, xc, ya);
            X[c] = fmaf( t0, ya, xc);
            Y[c] = fmaf(-t0, xa, yc);
        }
    }

    // --- pack over rho-bit4: X2[t] = (X[t], X[t+16]) ---
    u64 X2[16], Y2[16];
    #pragma unroll
    for (int t = 0; t < 16; t++) {
        F2PACK(X2[t], X[t], X[t + 16]);
        F2PACK(Y2[t], Y[t], Y[t + 16]);
    }

    // --- qubits 1..4: packed register stages, masks 15,7,3,1 ---
    #pragma unroll
    for (int q = 1; q < 5; q++) {
        const int i  = 4 - q;                        // r-bit index
        const int mu = (2 << i) - 1;                 // 15,7,3,1
        const u64 t2  = f2bcast(g_t[q]);
        const u64 nt2 = f2bcast(-g_t[q]);
        #pragma unroll
        for (int t = 0; t < 16; t++) {
            if (t & (1 << i)) continue;              // each pair once
            const int u = t ^ mu;
            u64 xa = X2[t], ya = Y2[t], xb = X2[u], yb = Y2[u];
            X2[t] = f2fma(t2,  yb, xa);
            Y2[t] = f2fma(nt2, xb, ya);
            X2[u] = f2fma(t2,  ya, xb);
            Y2[u] = f2fma(nt2, xa, yb);
        }
    }

    // --- qubits 5..9: lane-bit butterflies via 64-bit shfl_xor ---
    #pragma unroll
    for (int q = 5; q < 10; q++) {
        const int m = 1 << (9 - q);
        const u64 t2  = f2bcast(g_t[q]);
        const u64 nt2 = f2bcast(-g_t[q]);
        #pragma unroll
        for (int k = 0; k < 16; k++) {
            u64 oy = __shfl_xor_sync(0xFFFFFFFFu, Y2[k], m);
            u64 ox = __shfl_xor_sync(0xFFFFFFFFu, X2[k], m);
            X2[k] = f2fma(t2,  oy, X2[k]);
            Y2[k] = f2fma(nt2, ox, Y2[k]);
        }
    }

    // --- output: pairs are the two halves of each pack (mask rho^16) ---
    u64 accP = f2bcast(0.0f);
    float d = 0.0f;
    #pragma unroll
    for (int t = 0; t < 16; t++) {
        u64 P = f2fma(X2[t], X2[t], f2mul(Y2[t], Y2[t]));  // (|w0|^2, |w1|^2)
        accP = f2add(accP, P);
        float xl, xh, yl, yh;
        F2UNPACK(xl, xh, X2[t]);
        F2UNPACK(yl, yh, Y2[t]);
        d = fmaf(xl, xh, d);
        d = fmaf(yl, yh, d);
    }
    float A0, A1;
    F2UNPACK(A0, A1, accP);
    float acc = fmaf(g_ccoef, A1 - A0, g_scoef * d);
    #pragma unroll
    for (int o = 16; o; o >>= 1) acc += __shfl_xor_sync(0xFFFFFFFFu, acc, o);
    if (lane == 0) out[b] = acc;
}

extern "C" void kernel_launch(void* const* d_in, const int* in_sizes, int n_in,
                              void* d_out, int out_size) {
    const float* inputs = (const float*)d_in[0];   // [8192, 10]
    const float* weight = (const float*)d_in[1];   // [23]
    // d_in[2] = entangle_matrix: fixed CNOT cascade, replaced by closed-form perm
    float* out = (float*)d_out;                    // [8192]

    const int batch = in_sizes[0] / NQ;
    const int n_elems = in_sizes[0];

    k_pre<<<NBLK, 1024>>>(inputs, n_elems, weight);
    k_main<<<(batch + (NT / 32) - 1) / (NT / 32), NT>>>(inputs, out, batch);
}